// round 16
// baseline (speedup 1.0000x reference)
#include <cuda_runtime.h>
#include <cstdint>

// Conv2d via warp-level mma.sync tf32 implicit GEMM.
// input (64,8,256,256) f32 NCHW, filter (8,8,3,3) OIHW, VALID -> (64,8,254,254).
//
// R12: cross-strip software pipeline. Each CTA runs 4 strips of STRIP=4 rows
// with double-buffered smem; strip k+2 is staged via cp.async (raw f32, 16B)
// while strip k computes. The tf32 rna-round moves into the window load
// (LDS -> cvt -> reg), so math is bit-identical to R11. PLANE=792 === 24
// (mod 32) keeps all window LDS bank-conflict-free.

#define NTHREADS 256
#define STRIP    4
#define ROWS_S   (STRIP + 2)        // 6
#define COLS_P   132
#define PLANE    (ROWS_S * COLS_P)  // 792 floats (=== 24 mod 32: conflict-free)
#define BUF_FLOATS (8 * PLANE)      // 6336 floats = 25344 B
#define SMEM_FLOATS (2 * BUF_FLOATS)

__device__ __forceinline__ uint32_t tf32_bits(float x) {
    uint32_t u;
    asm("cvt.rna.tf32.f32 %0, %1;" : "=r"(u) : "f"(x));
    return u;
}

__global__ __launch_bounds__(NTHREADS, 4)
void Im2Col_Conv2d_6854767804820_kernel(const float* __restrict__ in,
                                        const float* __restrict__ filt,
                                        float* __restrict__ out)
{
    extern __shared__ float sm[];   // 2 buffers: [c][row 0..5][col 0..131] raw f32

    const int tid  = threadIdx.x;
    const int w    = tid >> 5;          // warp 0..7
    const int lane = tid & 31;
    const int g    = lane >> 2;         // groupID: pixel ofs / m index
    const int t    = lane & 3;          // threadID_in_group: c / k index

    const int q0   = blockIdx.x * 128;  // 0 or 128
    const int p0b  = blockIdx.y * (4 * STRIP);   // 0..240, 4 strips per CTA
    const int n    = blockIdx.z;

    const float* inN = in + (size_t)n * 524288;   // 8*256*256

    // ---- B fragments (rna-rounded): b[r][s][0]=filt[g][t][r][s], [1]=filt[g][t+4][r][s]
    uint32_t b[3][3][2];
#pragma unroll
    for (int r = 0; r < 3; r++)
#pragma unroll
        for (int s = 0; s < 3; s++) {
            b[r][s][0] = tf32_bits(__ldg(&filt[g * 72 + t * 9 + r * 3 + s]));
            b[r][s][1] = tf32_bits(__ldg(&filt[g * 72 + (t + 4) * 9 + r * 3 + s]));
        }

    // ---- async stage of one strip tile (raw f32): 8c x 6 rows x 33 float4 = 1584 jobs
    auto stage = [&](int sp0, int buf) {
        float* dst = sm + buf * BUF_FLOATS;
#pragma unroll
        for (int kk = 0; kk < 7; kk++) {
            int j = tid + kk * NTHREADS;
            if (j < 1584) {
                int c   = j / 198;
                int rem = j - c * 198;
                int row = rem / 33;
                int g4  = rem - row * 33;
                int gr  = sp0 + row; if (gr > 255) gr = 255;
                int gcb = q0 + g4 * 4; if (gcb > 252) gcb = 252;
                // clamped sources feed only outputs the store guards clip
                const float* src = inN + c * 65536 + gr * 256 + gcb;
                unsigned sa = (unsigned)__cvta_generic_to_shared(
                    dst + c * PLANE + row * COLS_P + g4 * 4);
                asm volatile("cp.async.ca.shared.global [%0], [%1], 16;"
                             :: "r"(sa), "l"(src));
            }
        }
        asm volatile("cp.async.commit_group;");
    };

    const int qw = w * 16;
    const int qg = q0 + qw + g;
    const int m0 = 2 * t;
    const int m1 = 2 * t + 1;
    float* outN = out + (size_t)n * 516128;      // 8*254*254

    // ---- compute one strip (4 rows) out of buffer `buf`
    auto compute = [&](int sp0, int buf) {
        const float* base = sm + buf * BUF_FLOATS + t * PLANE + qw + g;
        uint32_t win[3][12];   // [slot][k2*6 + px*3 + s], tf32 bits (rna)

#define LOAD_ROW(slot, j)                                                     \
        {                                                                     \
            const float* p_ = base + (j) * COLS_P;                            \
            _Pragma("unroll")                                                 \
            for (int k2_ = 0; k2_ < 2; k2_++)                                 \
                _Pragma("unroll")                                             \
                for (int px_ = 0; px_ < 2; px_++)                             \
                    _Pragma("unroll")                                         \
                    for (int s_ = 0; s_ < 3; s_++)                            \
                        win[slot][k2_ * 6 + px_ * 3 + s_] =                   \
                            tf32_bits(p_[k2_ * 4 * PLANE + px_ * 8 + s_]);    \
        }

        LOAD_ROW(0, 0)
        LOAD_ROW(1, 1)
        LOAD_ROW(2, 2)

#pragma unroll
        for (int i = 0; i < STRIP; i++) {
            float d0 = 0.f, d1 = 0.f, d2 = 0.f, d3 = 0.f;
#pragma unroll
            for (int r = 0; r < 3; r++) {
                const int slot = (i + r) % 3;    // compile-time (unrolled)
#pragma unroll
                for (int s = 0; s < 3; s++) {
                    asm volatile(
                        "mma.sync.aligned.m16n8k8.row.col.f32.tf32.tf32.f32 "
                        "{%0,%1,%2,%3}, {%4,%5,%6,%7}, {%8,%9}, {%0,%1,%2,%3};"
                        : "+f"(d0), "+f"(d1), "+f"(d2), "+f"(d3)
                        : "r"(win[slot][0 * 6 + 0 * 3 + s]),   // pix g,   k=t
                          "r"(win[slot][0 * 6 + 1 * 3 + s]),   // pix g+8, k=t
                          "r"(win[slot][1 * 6 + 0 * 3 + s]),   // pix g,   k=t+4
                          "r"(win[slot][1 * 6 + 1 * 3 + s]),   // pix g+8, k=t+4
                          "r"(b[r][s][0]), "r"(b[r][s][1]));
                }
            }

            if (sp0 + i < 254) {
                float* ob = outN + (size_t)(sp0 + i) * 254 + qg;
                if (qg < 254) {
                    ob[(size_t)m0 * 64516] = d0;
                    ob[(size_t)m1 * 64516] = d1;
                }
                if (qg + 8 < 254) {
                    ob[(size_t)m0 * 64516 + 8] = d2;
                    ob[(size_t)m1 * 64516 + 8] = d3;
                }
            }

            if (i < STRIP - 1) LOAD_ROW(i % 3, i + 3)
        }
#undef LOAD_ROW
    };

    // ---- pipeline: strips k = 0..3, buffers ping-pong, depth-2 prefetch
    stage(p0b,             0);
    stage(p0b + STRIP,     1);

    // k=0
    asm volatile("cp.async.wait_group 1;");   // buf0 ready
    __syncthreads();
    compute(p0b, 0);
    __syncthreads();                          // all reads of buf0 done
    stage(p0b + 2 * STRIP, 0);

    // k=1
    asm volatile("cp.async.wait_group 1;");   // buf1 ready
    __syncthreads();
    compute(p0b + STRIP, 1);
    __syncthreads();
    stage(p0b + 3 * STRIP, 1);

    // k=2
    asm volatile("cp.async.wait_group 1;");   // buf0 (strip 2) ready
    __syncthreads();
    compute(p0b + 2 * STRIP, 0);

    // k=3
    asm volatile("cp.async.wait_group 0;");   // buf1 (strip 3) ready
    __syncthreads();
    compute(p0b + 3 * STRIP, 1);
}

extern "C" void kernel_launch(void* const* d_in, const int* in_sizes, int n_in,
                              void* d_out, int out_size)
{
    const float* input  = (const float*)d_in[0];   // (64,8,256,256)
    const float* filter = (const float*)d_in[1];   // (8,8,3,3)
    float* output = (float*)d_out;                 // (64,8,254,254)

    static int attr_set = 0;
    if (!attr_set) {
        cudaFuncSetAttribute(Im2Col_Conv2d_6854767804820_kernel,
                             cudaFuncAttributeMaxDynamicSharedMemorySize,
                             SMEM_FLOATS * 4);
        attr_set = 1;
    }

    dim3 grid(2, 16, 64);   // q-half, 16-row super-strip (4x4), n
    Im2Col_Conv2d_6854767804820_kernel<<<grid, NTHREADS, SMEM_FLOATS * 4>>>(
        input, filter, output);
}

// round 17
// speedup vs baseline: 1.7498x; 1.7498x over previous
#include <cuda_runtime.h>
#include <cuda_fp16.h>
#include <cstdint>

// Conv2d via warp-level mma.sync fp16 implicit GEMM (f32 accumulate).
// input (64,8,256,256) f32 NCHW, filter (8,8,3,3) OIHW, VALID -> (64,8,254,254).
//
// R13: R11 structure, but m16n8k8.f16 instead of tf32. fp16 and tf32 have the
// SAME 10-bit mantissa (u = 2^-11), so precision is equivalent; f16 packs the
// two k (channel) values per thread into one half2 register:
//  - window loads: 6 LDS.32/row instead of 12
//  - smem halves -> STRIP=16 fits 4 CTAs/SM (38KB), halo overhead 1.125x
//  - staging stores half the bytes
// Smem = 4 channel-pair planes of half2, PLANE_E=2376 === 8 mod 32 keeps the
// t*8+g bank pattern conflict-free.

#define NTHREADS 256
#define STRIP    16
#define ROWS_S   (STRIP + 2)          // 18
#define COLS_P   132
#define PLANE_E  (ROWS_S * COLS_P)    // 2376 uint32 entries (=== 8 mod 32)
#define SMEM_U32 (4 * PLANE_E)        // 9504 entries = 38016 B

__global__ __launch_bounds__(NTHREADS, 4)
void Im2Col_Conv2d_6854767804820_kernel(const float* __restrict__ in,
                                        const float* __restrict__ filt,
                                        float* __restrict__ out)
{
    extern __shared__ uint32_t sm32[];  // [cpair 0..3][row 0..17][col 0..131] half2

    const int tid  = threadIdx.x;
    const int w    = tid >> 5;          // warp 0..7
    const int lane = tid & 31;
    const int g    = lane >> 2;         // groupID
    const int t    = lane & 3;          // threadID in group

    const int q0 = blockIdx.x * 128;    // 0 or 128
    const int p0 = blockIdx.y * STRIP;  // 0..240
    const int n  = blockIdx.z;

    const float* inN = in + (size_t)n * 524288;   // 8*256*256

    // ---- B fragments: b[r][s] = half2{ filt[m=g][c=2t][r][s], filt[m=g][c=2t+1][r][s] }
    // (B fragment: k = 2t,2t+1 packed lo/hi, n = g)
    uint32_t bf[3][3];
#pragma unroll
    for (int r = 0; r < 3; r++)
#pragma unroll
        for (int s = 0; s < 3; s++) {
            float w0 = __ldg(&filt[g * 72 + (2 * t)     * 9 + r * 3 + s]);
            float w1 = __ldg(&filt[g * 72 + (2 * t + 1) * 9 + r * 3 + s]);
            __half2 h = __floats2half2_rn(w0, w1);   // lo = even channel
            bf[r][s] = *reinterpret_cast<uint32_t*>(&h);
        }

    // ---- stage input tile as half2 channel pairs.
    // jobs: 4 cpairs x 18 rows x 33 col-quads = 2376.
    // job: read float4 from planes c=2j and c=2j+1, pack 4 half2, STS.128.
#pragma unroll
    for (int k = 0; k < 10; k++) {
        int j = tid + k * NTHREADS;
        if (j < 2376) {
            int cp  = j / 594;                 // channel pair 0..3
            int rem = j - cp * 594;
            int row = rem / 33;
            int g4  = rem - row * 33;
            int gr  = p0 + row;   if (gr > 255) gr = 255;
            int gcb = q0 + g4 * 4; if (gcb > 252) gcb = 252;
            // clamped sources feed only outputs the store guards clip
            const float* s0 = inN + (2 * cp)     * 65536 + gr * 256 + gcb;
            const float* s1 = inN + (2 * cp + 1) * 65536 + gr * 256 + gcb;
            float4 f0 = *reinterpret_cast<const float4*>(s0);
            float4 f1 = *reinterpret_cast<const float4*>(s1);
            __half2 h0 = __floats2half2_rn(f0.x, f1.x);
            __half2 h1 = __floats2half2_rn(f0.y, f1.y);
            __half2 h2 = __floats2half2_rn(f0.z, f1.z);
            __half2 h3 = __floats2half2_rn(f0.w, f1.w);
            uint4 u;
            u.x = *reinterpret_cast<uint32_t*>(&h0);
            u.y = *reinterpret_cast<uint32_t*>(&h1);
            u.z = *reinterpret_cast<uint32_t*>(&h2);
            u.w = *reinterpret_cast<uint32_t*>(&h3);
            reinterpret_cast<uint4*>(sm32)[j * 1] = u;   // entry j*4 -> uint4 slot j
        }
    }
    __syncthreads();

    // ---- compute
    const int qw = w * 16;
    const int qg = q0 + qw + g;
    const int m0 = 2 * t;
    const int m1 = 2 * t + 1;

    // thread t reads channel-pair plane t (its k = 2t,2t+1)
    const uint32_t* base = sm32 + t * PLANE_E + qw + g;

    // register window: win[slot][pix 0/1][s], half2 each; slot = row % 3
    uint32_t win[3][2][3];

#define LOAD_ROW(slot, j)                                                     \
    {                                                                         \
        const uint32_t* p_ = base + (j) * COLS_P;                             \
        _Pragma("unroll")                                                     \
        for (int px_ = 0; px_ < 2; px_++)                                     \
            _Pragma("unroll")                                                 \
            for (int s_ = 0; s_ < 3; s_++)                                    \
                win[slot][px_][s_] = p_[px_ * 8 + s_];                        \
    }

    LOAD_ROW(0, 0)
    LOAD_ROW(1, 1)
    LOAD_ROW(2, 2)

    float* outN = out + (size_t)n * 516128;      // 8*254*254

#pragma unroll
    for (int i = 0; i < STRIP; i++) {
        float d0 = 0.f, d1 = 0.f, d2 = 0.f, d3 = 0.f;

#pragma unroll
        for (int r = 0; r < 3; r++) {
            const int slot = (i + r) % 3;        // compile-time (unrolled)
#pragma unroll
            for (int s = 0; s < 3; s++) {
                asm volatile(
                    "mma.sync.aligned.m16n8k8.row.col.f32.f16.f16.f32 "
                    "{%0,%1,%2,%3}, {%4,%5}, {%6}, {%0,%1,%2,%3};"
                    : "+f"(d0), "+f"(d1), "+f"(d2), "+f"(d3)
                    : "r"(win[slot][0][s]),      // A row g   : pix g,   k=2t,2t+1
                      "r"(win[slot][1][s]),      // A row g+8 : pix g+8
                      "r"(bf[r][s]));
            }
        }

        // D: c0=(pix g, m0) c1=(pix g, m1) c2=(pix g+8, m0) c3=(pix g+8, m1)
        if (p0 + i < 254) {
            float* ob = outN + (size_t)(p0 + i) * 254 + qg;
            if (qg < 254) {
                ob[(size_t)m0 * 64516] = d0;
                ob[(size_t)m1 * 64516] = d1;
            }
            if (qg + 8 < 254) {
                ob[(size_t)m0 * 64516 + 8] = d2;
                ob[(size_t)m1 * 64516 + 8] = d3;
            }
        }

        if (i < STRIP - 1) LOAD_ROW(i % 3, i + 3)
    }
#undef LOAD_ROW
}

extern "C" void kernel_launch(void* const* d_in, const int* in_sizes, int n_in,
                              void* d_out, int out_size)
{
    const float* input  = (const float*)d_in[0];   // (64,8,256,256)
    const float* filter = (const float*)d_in[1];   // (8,8,3,3)
    float* output = (float*)d_out;                 // (64,8,254,254)

    static int attr_set = 0;
    if (!attr_set) {
        cudaFuncSetAttribute(Im2Col_Conv2d_6854767804820_kernel,
                             cudaFuncAttributeMaxDynamicSharedMemorySize,
                             SMEM_U32 * 4);
        attr_set = 1;
    }

    dim3 grid(2, 16, 64);   // q-half, p-strip, n
    Im2Col_Conv2d_6854767804820_kernel<<<grid, NTHREADS, SMEM_U32 * 4>>>(
        input, filter, output);
}